// round 1
// baseline (speedup 1.0000x reference)
#include <cuda_runtime.h>
#include <math.h>

#define NN 100000
#define EE 1600000
#define CC 32

// ---------------- scratch (static device globals; no allocation) -------------
__device__ float g_deg[NN];
__device__ float g_dis[NN];
__device__ float g_coef[EE];
__device__ float g_aggx[NN * CC];
__device__ float g_aggh[NN * CC];
__device__ float g_agghr[NN * CC];
__device__ float g_z[NN * CC];
__device__ float g_hr[NN * CC];

// ---------------- k0: zero accumulators -------------------------------------
__global__ void k_zero() {
    int i = blockIdx.x * blockDim.x + threadIdx.x;
    int stride = gridDim.x * blockDim.x;
    for (int j = i; j < NN; j += stride) g_deg[j] = 0.0f;
    const int M4 = NN * CC / 4;
    float4 z4 = make_float4(0.f, 0.f, 0.f, 0.f);
    float4* ax = reinterpret_cast<float4*>(g_aggx);
    float4* ah = reinterpret_cast<float4*>(g_aggh);
    float4* ar = reinterpret_cast<float4*>(g_agghr);
    for (int j = i; j < M4; j += stride) { ax[j] = z4; ah[j] = z4; ar[j] = z4; }
}

// ---------------- k1: degree scatter (segment_sum of w over src) ------------
__global__ void k_deg(const int* __restrict__ ei, const float* __restrict__ w) {
    int e = blockIdx.x * blockDim.x + threadIdx.x;
    if (e >= EE) return;
    atomicAdd(&g_deg[ei[e]], w[e]);
}

// ---------------- k2: inverse sqrt degree ------------------------------------
__global__ void k_dis() {
    int n = blockIdx.x * blockDim.x + threadIdx.x;
    if (n >= NN) return;
    float d = g_deg[n];
    g_dis[n] = (d > 0.0f) ? rsqrtf(d) : 0.0f;
}

// ---------------- k3: edge coefficients --------------------------------------
__global__ void k_coef(const int* __restrict__ ei, const float* __restrict__ w) {
    int e = blockIdx.x * blockDim.x + threadIdx.x;
    if (e >= EE) return;
    int s = ei[e];
    int d = ei[EE + e];
    g_coef[e] = -(g_dis[s] * w[e] * g_dis[d]);
}

// ---------------- k4: scatter x and h (8 threads per edge, float4) ----------
__global__ void k_scatter_xh(const int* __restrict__ ei,
                             const float4* __restrict__ x4,
                             const float4* __restrict__ h4) {
    int tid = blockIdx.x * blockDim.x + threadIdx.x;
    int e = tid >> 3;
    int p = tid & 7;
    if (e >= EE) return;
    int s = __ldg(&ei[e]);
    int d = __ldg(&ei[EE + e]);
    float c = __ldg(&g_coef[e]);
    float4 xv = __ldg(&x4[s * 8 + p]);
    float4 hv = __ldg(&h4[s * 8 + p]);
    float4 xs = make_float4(c * xv.x, c * xv.y, c * xv.z, c * xv.w);
    float4 hs = make_float4(c * hv.x, c * hv.y, c * hv.z, c * hv.w);
    float4* ax = reinterpret_cast<float4*>(g_aggx);
    float4* ah = reinterpret_cast<float4*>(g_aggh);
    atomicAdd(&ax[d * 8 + p], xs);   // sm_90+: 16B vector red
    atomicAdd(&ah[d * 8 + p], hs);
}

// ---------------- k5: node pass 1 -> z, h*r ----------------------------------
// gate_g = x@Wx[g,0] + aggx@Wx[g,1] + bx[g] + h@Wh[g,0] + aggh@Wh[g,1] + bh[g]
__global__ void k_gates_zr(const float* __restrict__ x,
                           const float* __restrict__ h,
                           const float* __restrict__ Wx,
                           const float* __restrict__ bx,
                           const float* __restrict__ Wh,
                           const float* __restrict__ bh) {
    __shared__ float sWx[4096];  // Wx[0..1][0..1][32][32]
    __shared__ float sWh[4096];  // Wh[0..1][0..1][32][32]
    int tid = threadIdx.x;
    for (int i = tid; i < 4096; i += blockDim.x) {
        sWx[i] = Wx[i];
        sWh[i] = Wh[i];
    }
    __syncthreads();

    int lane = tid & 31;
    int warp = tid >> 5;
    int node = blockIdx.x * (blockDim.x >> 5) + warp;
    if (node >= NN) return;

    int base = node * CC + lane;
    float xv = x[base];
    float hv = h[base];
    float ax = g_aggx[base];
    float ah = g_aggh[base];

    float acc0 = bx[lane] + bh[lane];             // gate z
    float acc1 = bx[32 + lane] + bh[32 + lane];   // gate r

#pragma unroll
    for (int k = 0; k < 32; k++) {
        float xk = __shfl_sync(0xffffffffu, xv, k);
        float axk = __shfl_sync(0xffffffffu, ax, k);
        float hk = __shfl_sync(0xffffffffu, hv, k);
        float ahk = __shfl_sync(0xffffffffu, ah, k);
        int row = k * 32 + lane;
        acc0 += xk * sWx[row] + axk * sWx[1024 + row]
              + hk * sWh[row] + ahk * sWh[1024 + row];
        acc1 += xk * sWx[2048 + row] + axk * sWx[3072 + row]
              + hk * sWh[2048 + row] + ahk * sWh[3072 + row];
    }
    float z = 1.0f / (1.0f + expf(-acc0));
    float r = 1.0f / (1.0f + expf(-acc1));
    g_z[base] = z;
    g_hr[base] = hv * r;
}

// ---------------- k6: scatter h*r --------------------------------------------
__global__ void k_scatter_hr(const int* __restrict__ ei) {
    int tid = blockIdx.x * blockDim.x + threadIdx.x;
    int e = tid >> 3;
    int p = tid & 7;
    if (e >= EE) return;
    int s = __ldg(&ei[e]);
    int d = __ldg(&ei[EE + e]);
    float c = __ldg(&g_coef[e]);
    const float4* hr4 = reinterpret_cast<const float4*>(g_hr);
    float4 v = __ldg(&hr4[s * 8 + p]);
    float4 vs = make_float4(c * v.x, c * v.y, c * v.z, c * v.w);
    float4* ar = reinterpret_cast<float4*>(g_agghr);
    atomicAdd(&ar[d * 8 + p], vs);
}

// ---------------- k7: node pass 2 -> h_new, out ------------------------------
__global__ void k_final(const float* __restrict__ x,
                        const float* __restrict__ h,
                        const float* __restrict__ Wx,
                        const float* __restrict__ bx,
                        const float* __restrict__ Wh,
                        const float* __restrict__ bh,
                        const float* __restrict__ Wl,
                        const float* __restrict__ bl,
                        float* __restrict__ out) {
    __shared__ float sWx[2048];  // Wx[2][0..1][32][32]
    __shared__ float sWh[2048];
    __shared__ float sWl[32];
    int tid = threadIdx.x;
    for (int i = tid; i < 2048; i += blockDim.x) {
        sWx[i] = Wx[4096 + i];
        sWh[i] = Wh[4096 + i];
    }
    if (tid < 32) sWl[tid] = Wl[tid];
    __syncthreads();

    int lane = tid & 31;
    int warp = tid >> 5;
    int node = blockIdx.x * (blockDim.x >> 5) + warp;
    if (node >= NN) return;

    int base = node * CC + lane;
    float xv = x[base];
    float hrv = g_hr[base];
    float ax = g_aggx[base];
    float ahr = g_agghr[base];

    float acc = bx[64 + lane] + bh[64 + lane];
#pragma unroll
    for (int k = 0; k < 32; k++) {
        float xk = __shfl_sync(0xffffffffu, xv, k);
        float axk = __shfl_sync(0xffffffffu, ax, k);
        float hrk = __shfl_sync(0xffffffffu, hrv, k);
        float ahrk = __shfl_sync(0xffffffffu, ahr, k);
        int row = k * 32 + lane;
        acc += xk * sWx[row] + axk * sWx[1024 + row]
             + hrk * sWh[row] + ahrk * sWh[1024 + row];
    }
    float ht = tanhf(acc);
    float zv = g_z[base];
    float hv = h[base];
    float hn = zv * hv + (1.0f - zv) * ht;

    // h_new goes after out[N] in the flat output
    out[NN + base] = hn;

    // linear head: s = relu(hn) . Wl + bl ; out = softplus(s)
    float rl = fmaxf(hn, 0.0f) * sWl[lane];
#pragma unroll
    for (int off = 16; off > 0; off >>= 1)
        rl += __shfl_xor_sync(0xffffffffu, rl, off);
    if (lane == 0) {
        float s = rl + bl[0];
        // numerically stable softplus
        out[node] = log1pf(expf(-fabsf(s))) + fmaxf(s, 0.0f);
    }
}

// ---------------- launch ------------------------------------------------------
extern "C" void kernel_launch(void* const* d_in, const int* in_sizes, int n_in,
                              void* d_out, int out_size) {
    const float* x  = (const float*)d_in[0];
    const int*   ei = (const int*)d_in[1];
    const float* w  = (const float*)d_in[2];
    const float* h  = (const float*)d_in[3];
    const float* Wx = (const float*)d_in[4];
    const float* bx = (const float*)d_in[5];
    const float* Wh = (const float*)d_in[6];
    const float* bh = (const float*)d_in[7];
    const float* Wl = (const float*)d_in[8];
    const float* bl = (const float*)d_in[9];
    float* out = (float*)d_out;

    (void)in_sizes; (void)n_in; (void)out_size;

    k_zero<<<2048, 256>>>();
    k_deg<<<(EE + 255) / 256, 256>>>(ei, w);
    k_dis<<<(NN + 255) / 256, 256>>>();
    k_coef<<<(EE + 255) / 256, 256>>>(ei, w);
    k_scatter_xh<<<(EE * 8 + 255) / 256, 256>>>(
        ei, (const float4*)x, (const float4*)h);
    k_gates_zr<<<(NN + 7) / 8, 256>>>(x, h, Wx, bx, Wh, bh);
    k_scatter_hr<<<(EE * 8 + 255) / 256, 256>>>(ei);
    k_final<<<(NN + 7) / 8, 256>>>(x, h, Wx, bx, Wh, bh, Wl, bl, out);
}

// round 2
// speedup vs baseline: 1.2036x; 1.2036x over previous
#include <cuda_runtime.h>
#include <math.h>

#define NN 100000
#define EE 1600000
#define CC 32
#define SCAN_T 512
#define NB ((NN + SCAN_T - 1) / SCAN_T)   /* 196 */

// ---------------- scratch (static device globals; no allocation) -------------
__device__ float g_deg[NN];
__device__ int   g_cnt[NN];
__device__ int   g_row[NN + 1];
__device__ int   g_cur[NN];
__device__ int   g_part[256];
__device__ int2  g_csr[EE];          // (src, coef bits), grouped by dst
__device__ float g_aggx[NN * CC];
__device__ float g_z[NN * CC];
__device__ float g_hr[NN * CC];

// ---------------- f32x2 packed-FMA helpers -----------------------------------
__device__ __forceinline__ unsigned long long pack2(float a, float b) {
    unsigned long long v;
    asm("mov.b64 %0, {%1, %2};" : "=l"(v) : "f"(a), "f"(b));
    return v;
}
__device__ __forceinline__ float2 unpack2(unsigned long long v) {
    float2 r;
    asm("mov.b64 {%0, %1}, %2;" : "=f"(r.x), "=f"(r.y) : "l"(v));
    return r;
}
__device__ __forceinline__ void fma2(unsigned long long& acc, float2 w,
                                     float s0, float s1) {
    unsigned long long wv = pack2(w.x, w.y);
    unsigned long long sv = pack2(s0, s1);
    asm("fma.rn.f32x2 %0, %1, %2, %3;" : "=l"(acc) : "l"(wv), "l"(sv), "l"(acc));
}

// ---------------- k_init: zero deg/cnt, seal row[] ---------------------------
__global__ void k_init() {
    int i = blockIdx.x * blockDim.x + threadIdx.x;
    if (i < NN) { g_deg[i] = 0.0f; g_cnt[i] = 0; }
    if (i == 0) g_row[NN] = EE;
}

// ---------------- k_deg_hist: deg over src + in-degree histogram over dst ----
__global__ void k_deg_hist(const int* __restrict__ ei, const float* __restrict__ w) {
    int e = blockIdx.x * blockDim.x + threadIdx.x;
    if (e >= EE) return;
    int s = ei[e];
    int d = ei[EE + e];
    atomicAdd(&g_deg[s], w[e]);
    atomicAdd(&g_cnt[d], 1);
}

// ---------------- k_scan1: per-block partial sums of cnt ---------------------
__global__ void k_scan1() {
    __shared__ int s[SCAN_T];
    int t = threadIdx.x;
    int i = blockIdx.x * SCAN_T + t;
    s[t] = (i < NN) ? g_cnt[i] : 0;
    __syncthreads();
    for (int off = SCAN_T / 2; off > 0; off >>= 1) {
        if (t < off) s[t] += s[t + off];
        __syncthreads();
    }
    if (t == 0) g_part[blockIdx.x] = s[0];
}

// ---------------- k_scan2: exclusive scan of 196 partials (1 block) ---------
__global__ void k_scan2() {
    __shared__ int s[256];
    int t = threadIdx.x;
    int v = (t < NB) ? g_part[t] : 0;
    s[t] = v;
    __syncthreads();
    for (int off = 1; off < 256; off <<= 1) {
        int a = (t >= off) ? s[t - off] : 0;
        __syncthreads();
        s[t] += a;
        __syncthreads();
    }
    if (t < NB) g_part[t] = s[t] - v;   // exclusive
}

// ---------------- k_scan3: block-level exclusive scan -> row[], cur[] --------
__global__ void k_scan3() {
    __shared__ int s[SCAN_T];
    int t = threadIdx.x;
    int i = blockIdx.x * SCAN_T + t;
    int v = (i < NN) ? g_cnt[i] : 0;
    s[t] = v;
    __syncthreads();
    for (int off = 1; off < SCAN_T; off <<= 1) {
        int a = (t >= off) ? s[t - off] : 0;
        __syncthreads();
        s[t] += a;
        __syncthreads();
    }
    if (i < NN) {
        int rs = g_part[blockIdx.x] + s[t] - v;   // exclusive within chunk
        g_row[i] = rs;
        g_cur[i] = rs;
    }
}

// ---------------- k_place: compute coef, place edge into CSR slot ------------
__global__ void k_place(const int* __restrict__ ei, const float* __restrict__ w) {
    int e = blockIdx.x * blockDim.x + threadIdx.x;
    if (e >= EE) return;
    int s = ei[e];
    int d = ei[EE + e];
    float ds = g_deg[s];
    float dd = g_deg[d];
    float cs = (ds > 0.0f) ? rsqrtf(ds) : 0.0f;
    float cd = (dd > 0.0f) ? rsqrtf(dd) : 0.0f;
    float coef = -(cs * w[e] * cd);
    int pos = atomicAdd(&g_cur[d], 1);
    g_csr[pos] = make_int2(s, __float_as_int(coef));
}

// ---------------- k_gates: fused gather(x,h) + gates z,r ---------------------
// gate_g = x@Wx[g,0] + aggx@Wx[g,1] + bx[g] + h@Wh[g,0] + aggh@Wh[g,1] + bh[g]
__global__ void __launch_bounds__(512) k_gates(
        const float* __restrict__ x, const float* __restrict__ h,
        const float* __restrict__ Wx, const float* __restrict__ bx,
        const float* __restrict__ Wh, const float* __restrict__ bh) {
    // pair-packed weights: (.x = gate z, .y = gate r)
    __shared__ float2 sPx0[1024], sPx1[1024], sPh0[1024], sPh1[1024];
    int tid = threadIdx.x;
    for (int i = tid; i < 1024; i += blockDim.x) {
        sPx0[i] = make_float2(Wx[i],        Wx[2048 + i]);
        sPx1[i] = make_float2(Wx[1024 + i], Wx[3072 + i]);
        sPh0[i] = make_float2(Wh[i],        Wh[2048 + i]);
        sPh1[i] = make_float2(Wh[1024 + i], Wh[3072 + i]);
    }
    __syncthreads();

    int lane = tid & 31;
    int warp = tid >> 5;
    int wpb = blockDim.x >> 5;
    float bz = bx[lane] + bh[lane];
    float br = bx[32 + lane] + bh[32 + lane];

    for (int node = blockIdx.x * wpb + warp; node < NN; node += gridDim.x * wpb) {
        int base = node * CC + lane;
        float xv = x[base];
        float hv = h[base];

        // gather in-edges: ax = sum coef*x[src], ah = sum coef*h[src]
        int beg = g_row[node], end = g_row[node + 1];
        float ax = 0.0f, ah = 0.0f;
        int e = beg;
        for (; e + 4 <= end; e += 4) {
            int2 t0 = g_csr[e], t1 = g_csr[e + 1], t2 = g_csr[e + 2], t3 = g_csr[e + 3];
            float c0 = __int_as_float(t0.y), c1 = __int_as_float(t1.y);
            float c2 = __int_as_float(t2.y), c3 = __int_as_float(t3.y);
            float x0 = x[t0.x * CC + lane], x1 = x[t1.x * CC + lane];
            float x2 = x[t2.x * CC + lane], x3 = x[t3.x * CC + lane];
            float h0 = h[t0.x * CC + lane], h1 = h[t1.x * CC + lane];
            float h2 = h[t2.x * CC + lane], h3 = h[t3.x * CC + lane];
            ax += c0 * x0 + c1 * x1 + c2 * x2 + c3 * x3;
            ah += c0 * h0 + c1 * h1 + c2 * h2 + c3 * h3;
        }
        for (; e < end; e++) {
            int2 t = g_csr[e];
            float c = __int_as_float(t.y);
            ax += c * x[t.x * CC + lane];
            ah += c * h[t.x * CC + lane];
        }

        // dual-gate GEMM in f32x2
        unsigned long long acc = pack2(bz, br);
#pragma unroll
        for (int k = 0; k < 32; k++) {
            float xk  = __shfl_sync(0xffffffffu, xv, k);
            float axk = __shfl_sync(0xffffffffu, ax, k);
            float hk  = __shfl_sync(0xffffffffu, hv, k);
            float ahk = __shfl_sync(0xffffffffu, ah, k);
            int row = k * 32 + lane;
            fma2(acc, sPx0[row], xk, xk);
            fma2(acc, sPx1[row], axk, axk);
            fma2(acc, sPh0[row], hk, hk);
            fma2(acc, sPh1[row], ahk, ahk);
        }
        float2 a = unpack2(acc);
        float z = 1.0f / (1.0f + expf(-a.x));
        float r = 1.0f / (1.0f + expf(-a.y));
        g_z[base] = z;
        g_hr[base] = hv * r;
        g_aggx[base] = ax;
    }
}

// ---------------- k_final: fused gather(hr) + h_tilde + h_new + head ---------
__global__ void __launch_bounds__(512) k_final(
        const float* __restrict__ x, const float* __restrict__ h,
        const float* __restrict__ Wx, const float* __restrict__ bx,
        const float* __restrict__ Wh, const float* __restrict__ bh,
        const float* __restrict__ Wl, const float* __restrict__ bl,
        float* __restrict__ out) {
    // k-pair-packed weights for gate 2: (.x = even k, .y = odd k)
    __shared__ float2 sQx0[512], sQx1[512], sQh0[512], sQh1[512];
    __shared__ float sWl[32];
    int tid = threadIdx.x;
    for (int i = tid; i < 512; i += blockDim.x) {
        int t = i >> 5, c = i & 31;
        int o = t * 64 + c;
        sQx0[i] = make_float2(Wx[4096 + o], Wx[4096 + o + 32]);
        sQx1[i] = make_float2(Wx[5120 + o], Wx[5120 + o + 32]);
        sQh0[i] = make_float2(Wh[4096 + o], Wh[4096 + o + 32]);
        sQh1[i] = make_float2(Wh[5120 + o], Wh[5120 + o + 32]);
    }
    if (tid < 32) sWl[tid] = Wl[tid];
    __syncthreads();

    int lane = tid & 31;
    int warp = tid >> 5;
    int wpb = blockDim.x >> 5;
    float bias = bx[64 + lane] + bh[64 + lane];
    float blv = bl[0];

    for (int node = blockIdx.x * wpb + warp; node < NN; node += gridDim.x * wpb) {
        int base = node * CC + lane;
        float xv  = x[base];
        float hrv = g_hr[base];
        float axv = g_aggx[base];

        // gather in-edges of hr
        int beg = g_row[node], end = g_row[node + 1];
        float ahr = 0.0f;
        int e = beg;
        for (; e + 4 <= end; e += 4) {
            int2 t0 = g_csr[e], t1 = g_csr[e + 1], t2 = g_csr[e + 2], t3 = g_csr[e + 3];
            float v0 = g_hr[t0.x * CC + lane], v1 = g_hr[t1.x * CC + lane];
            float v2 = g_hr[t2.x * CC + lane], v3 = g_hr[t3.x * CC + lane];
            ahr += __int_as_float(t0.y) * v0 + __int_as_float(t1.y) * v1
                 + __int_as_float(t2.y) * v2 + __int_as_float(t3.y) * v3;
        }
        for (; e < end; e++) {
            int2 t = g_csr[e];
            ahr += __int_as_float(t.y) * g_hr[t.x * CC + lane];
        }

        // single-gate GEMM: split accumulation over even/odd k in f32x2
        unsigned long long acc = pack2(bias, 0.0f);
#pragma unroll
        for (int t = 0; t < 16; t++) {
            int k0 = 2 * t, k1 = 2 * t + 1;
            float xa = __shfl_sync(0xffffffffu, xv, k0);
            float xb = __shfl_sync(0xffffffffu, xv, k1);
            float aa = __shfl_sync(0xffffffffu, axv, k0);
            float ab = __shfl_sync(0xffffffffu, axv, k1);
            float ha = __shfl_sync(0xffffffffu, hrv, k0);
            float hb = __shfl_sync(0xffffffffu, hrv, k1);
            float ra = __shfl_sync(0xffffffffu, ahr, k0);
            float rb = __shfl_sync(0xffffffffu, ahr, k1);
            int idx = t * 32 + lane;
            fma2(acc, sQx0[idx], xa, xb);
            fma2(acc, sQx1[idx], aa, ab);
            fma2(acc, sQh0[idx], ha, hb);
            fma2(acc, sQh1[idx], ra, rb);
        }
        float2 a2 = unpack2(acc);
        float pre = a2.x + a2.y;
        float ht = tanhf(pre);
        float zv = g_z[base];
        float hv = h[base];
        float hn = zv * hv + (1.0f - zv) * ht;

        out[NN + base] = hn;

        float rl = fmaxf(hn, 0.0f) * sWl[lane];
#pragma unroll
        for (int off = 16; off > 0; off >>= 1)
            rl += __shfl_xor_sync(0xffffffffu, rl, off);
        if (lane == 0) {
            float s = rl + blv;
            out[node] = log1pf(expf(-fabsf(s))) + fmaxf(s, 0.0f);
        }
    }
}

// ---------------- launch ------------------------------------------------------
extern "C" void kernel_launch(void* const* d_in, const int* in_sizes, int n_in,
                              void* d_out, int out_size) {
    const float* x  = (const float*)d_in[0];
    const int*   ei = (const int*)d_in[1];
    const float* w  = (const float*)d_in[2];
    const float* h  = (const float*)d_in[3];
    const float* Wx = (const float*)d_in[4];
    const float* bx = (const float*)d_in[5];
    const float* Wh = (const float*)d_in[6];
    const float* bh = (const float*)d_in[7];
    const float* Wl = (const float*)d_in[8];
    const float* bl = (const float*)d_in[9];
    float* out = (float*)d_out;

    (void)in_sizes; (void)n_in; (void)out_size;

    k_init<<<NB, SCAN_T>>>();
    k_deg_hist<<<(EE + 255) / 256, 256>>>(ei, w);
    k_scan1<<<NB, SCAN_T>>>();
    k_scan2<<<1, 256>>>();
    k_scan3<<<NB, SCAN_T>>>();
    k_place<<<(EE + 255) / 256, 256>>>(ei, w);
    k_gates<<<444, 512>>>(x, h, Wx, bx, Wh, bh);
    k_final<<<444, 512>>>(x, h, Wx, bx, Wh, bh, Wl, bl, out);
}

// round 3
// speedup vs baseline: 1.5557x; 1.2926x over previous
#include <cuda_runtime.h>
#include <math.h>

#define NN 100000
#define EE 1600000
#define CC 32
#define SCAN_T 512
#define NB ((NN + SCAN_T - 1) / SCAN_T)   /* 196 */

// ---------------- scratch (static device globals; no allocation) -------------
__device__ float g_deg[NN];
__device__ int   g_cnt[NN];
__device__ int   g_row[NN + 1];
__device__ int   g_cur[NN];
__device__ int   g_part[256];
__device__ int2  g_csr[EE];          // (src, coef bits), grouped by dst
__device__ float g_aggx[NN * CC];
__device__ float g_z[NN * CC];
__device__ float g_hr[NN * CC];

// ---------------- f32x2 packed-FMA helpers -----------------------------------
__device__ __forceinline__ unsigned long long pack2(float a, float b) {
    unsigned long long v;
    asm("mov.b64 %0, {%1, %2};" : "=l"(v) : "f"(a), "f"(b));
    return v;
}
__device__ __forceinline__ float2 unpack2(unsigned long long v) {
    float2 r;
    asm("mov.b64 {%0, %1}, %2;" : "=f"(r.x), "=f"(r.y) : "l"(v));
    return r;
}
__device__ __forceinline__ void fma2(unsigned long long& acc, float2 w,
                                     float s0, float s1) {
    unsigned long long wv = pack2(w.x, w.y);
    unsigned long long sv = pack2(s0, s1);
    asm("fma.rn.f32x2 %0, %1, %2, %3;" : "=l"(acc) : "l"(wv), "l"(sv), "l"(acc));
}

// ---------------- k_init ------------------------------------------------------
__global__ void k_init() {
    int i = blockIdx.x * blockDim.x + threadIdx.x;
    if (i < NN) { g_deg[i] = 0.0f; g_cnt[i] = 0; }
    if (i == 0) g_row[NN] = EE;
}

// ---------------- k_deg_hist: weighted out-deg over src + in-deg hist over dst
__global__ void k_deg_hist(const int* __restrict__ ei, const float* __restrict__ w) {
    int e = blockIdx.x * blockDim.x + threadIdx.x;
    if (e >= EE) return;
    int s = ei[e];
    int d = ei[EE + e];
    atomicAdd(&g_deg[s], w[e]);
    atomicAdd(&g_cnt[d], 1);
}

// ---------------- scans -------------------------------------------------------
__global__ void k_scan1() {
    __shared__ int s[SCAN_T];
    int t = threadIdx.x;
    int i = blockIdx.x * SCAN_T + t;
    s[t] = (i < NN) ? g_cnt[i] : 0;
    __syncthreads();
    for (int off = SCAN_T / 2; off > 0; off >>= 1) {
        if (t < off) s[t] += s[t + off];
        __syncthreads();
    }
    if (t == 0) g_part[blockIdx.x] = s[0];
}

__global__ void k_scan2() {
    __shared__ int s[256];
    int t = threadIdx.x;
    int v = (t < NB) ? g_part[t] : 0;
    s[t] = v;
    __syncthreads();
    for (int off = 1; off < 256; off <<= 1) {
        int a = (t >= off) ? s[t - off] : 0;
        __syncthreads();
        s[t] += a;
        __syncthreads();
    }
    if (t < NB) g_part[t] = s[t] - v;   // exclusive
}

__global__ void k_scan3() {
    __shared__ int s[SCAN_T];
    int t = threadIdx.x;
    int i = blockIdx.x * SCAN_T + t;
    int v = (i < NN) ? g_cnt[i] : 0;
    s[t] = v;
    __syncthreads();
    for (int off = 1; off < SCAN_T; off <<= 1) {
        int a = (t >= off) ? s[t - off] : 0;
        __syncthreads();
        s[t] += a;
        __syncthreads();
    }
    if (i < NN) {
        int rs = g_part[blockIdx.x] + s[t] - v;
        g_row[i] = rs;
        g_cur[i] = rs;
    }
}

// ---------------- k_place: coef + CSR placement -------------------------------
__global__ void k_place(const int* __restrict__ ei, const float* __restrict__ w) {
    int e = blockIdx.x * blockDim.x + threadIdx.x;
    if (e >= EE) return;
    int s = ei[e];
    int d = ei[EE + e];
    float ds = g_deg[s];
    float dd = g_deg[d];
    float cs = (ds > 0.0f) ? rsqrtf(ds) : 0.0f;
    float cd = (dd > 0.0f) ? rsqrtf(dd) : 0.0f;
    float coef = -(cs * w[e] * cd);
    int pos = atomicAdd(&g_cur[d], 1);
    g_csr[pos] = make_int2(s, __float_as_int(coef));
}

// ---------------- per-node gather helper --------------------------------------
__device__ __forceinline__ void gather2(int node, int lane,
                                        const float* __restrict__ a,
                                        const float* __restrict__ b,
                                        float& ra, float& rb) {
    int beg = g_row[node], end = g_row[node + 1];
    float sa = 0.0f, sb = 0.0f;
    int e = beg;
    for (; e + 4 <= end; e += 4) {
        int2 t0 = g_csr[e], t1 = g_csr[e + 1], t2 = g_csr[e + 2], t3 = g_csr[e + 3];
        float c0 = __int_as_float(t0.y), c1 = __int_as_float(t1.y);
        float c2 = __int_as_float(t2.y), c3 = __int_as_float(t3.y);
        float a0 = a[t0.x * CC + lane], a1 = a[t1.x * CC + lane];
        float a2 = a[t2.x * CC + lane], a3 = a[t3.x * CC + lane];
        float b0 = b[t0.x * CC + lane], b1 = b[t1.x * CC + lane];
        float b2 = b[t2.x * CC + lane], b3 = b[t3.x * CC + lane];
        sa += c0 * a0 + c1 * a1 + c2 * a2 + c3 * a3;
        sb += c0 * b0 + c1 * b1 + c2 * b2 + c3 * b3;
    }
    for (; e < end; e++) {
        int2 t = g_csr[e];
        float c = __int_as_float(t.y);
        sa += c * a[t.x * CC + lane];
        sb += c * b[t.x * CC + lane];
    }
    ra = sa; rb = sb;
}

__device__ __forceinline__ void gather1(int node, int lane,
                                        const float* __restrict__ a, float& ra) {
    int beg = g_row[node], end = g_row[node + 1];
    float sa = 0.0f;
    int e = beg;
    for (; e + 4 <= end; e += 4) {
        int2 t0 = g_csr[e], t1 = g_csr[e + 1], t2 = g_csr[e + 2], t3 = g_csr[e + 3];
        sa += __int_as_float(t0.y) * a[t0.x * CC + lane]
            + __int_as_float(t1.y) * a[t1.x * CC + lane]
            + __int_as_float(t2.y) * a[t2.x * CC + lane]
            + __int_as_float(t3.y) * a[t3.x * CC + lane];
    }
    for (; e < end; e++) {
        int2 t = g_csr[e];
        sa += __int_as_float(t.y) * a[t.x * CC + lane];
    }
    ra = sa;
}

// ---------------- k_gates: fused gather(x,h) + gates z,r (4 nodes/warp) ------
// gate_g = x@Wx[g,0] + aggx@Wx[g,1] + h@Wh[g,0] + aggh@Wh[g,1] + bx[g] + bh[g]
__global__ void __launch_bounds__(256) k_gates(
        const float* __restrict__ x, const float* __restrict__ h,
        const float* __restrict__ Wx, const float* __restrict__ bx,
        const float* __restrict__ Wh, const float* __restrict__ bh) {
    // pair-packed weights (.x = gate z, .y = gate r), k-major
    __shared__ float2 sW[4][1024];       // [mat][k*32+lane]
    __shared__ float  sIn[8 * 4 * 4 * 32]; // [warp][node][arr][lane]
    int tid = threadIdx.x;
    for (int i = tid; i < 1024; i += blockDim.x) {
        sW[0][i] = make_float2(Wx[i],        Wx[2048 + i]);
        sW[1][i] = make_float2(Wx[1024 + i], Wx[3072 + i]);
        sW[2][i] = make_float2(Wh[i],        Wh[2048 + i]);
        sW[3][i] = make_float2(Wh[1024 + i], Wh[3072 + i]);
    }
    __syncthreads();

    int lane = tid & 31;
    int warp = tid >> 5;
    float bz = bx[lane] + bh[lane];
    float br = bx[32 + lane] + bh[32 + lane];

    int gw = blockIdx.x * 8 + warp;          // global warp id
    int stride = gridDim.x * 8 * 4;
    float* stage = &sIn[warp * 512];

    for (int nb = gw * 4; nb < NN; nb += stride) {
        float hv[4], axr[4];
        // ---- stage inputs for up to 4 nodes ----
#pragma unroll
        for (int i = 0; i < 4; i++) {
            int node = nb + i;
            float xv = 0.f, hvv = 0.f, ax = 0.f, ah = 0.f;
            if (node < NN) {
                int base = node * CC + lane;
                xv = x[base];
                hvv = h[base];
                gather2(node, lane, x, h, ax, ah);
            }
            hv[i] = hvv; axr[i] = ax;
            stage[i * 128 +   0 + lane] = xv;
            stage[i * 128 +  32 + lane] = ax;
            stage[i * 128 +  64 + lane] = hvv;
            stage[i * 128 +  96 + lane] = ah;
        }
        __syncwarp();

        unsigned long long acc0 = pack2(bz, br);
        unsigned long long acc1 = acc0, acc2 = acc0, acc3 = acc0;
        const float4* st4 = (const float4*)stage;

#pragma unroll
        for (int q = 0; q < 8; q++) {
            float2 w[4][4];
#pragma unroll
            for (int kk = 0; kk < 4; kk++) {
                int row = (q * 4 + kk) * 32 + lane;
                w[kk][0] = sW[0][row];
                w[kk][1] = sW[1][row];
                w[kk][2] = sW[2][row];
                w[kk][3] = sW[3][row];
            }
#pragma unroll
            for (int i = 0; i < 4; i++) {
                unsigned long long a = (i == 0) ? acc0 : (i == 1) ? acc1 : (i == 2) ? acc2 : acc3;
                float4 vx = st4[i * 32 + 0 + q];
                float4 va = st4[i * 32 + 8 + q];
                float4 vh = st4[i * 32 + 16 + q];
                float4 vr = st4[i * 32 + 24 + q];
                fma2(a, w[0][0], vx.x, vx.x); fma2(a, w[0][1], va.x, va.x);
                fma2(a, w[0][2], vh.x, vh.x); fma2(a, w[0][3], vr.x, vr.x);
                fma2(a, w[1][0], vx.y, vx.y); fma2(a, w[1][1], va.y, va.y);
                fma2(a, w[1][2], vh.y, vh.y); fma2(a, w[1][3], vr.y, vr.y);
                fma2(a, w[2][0], vx.z, vx.z); fma2(a, w[2][1], va.z, va.z);
                fma2(a, w[2][2], vh.z, vh.z); fma2(a, w[2][3], vr.z, vr.z);
                fma2(a, w[3][0], vx.w, vx.w); fma2(a, w[3][1], va.w, va.w);
                fma2(a, w[3][2], vh.w, vh.w); fma2(a, w[3][3], vr.w, vr.w);
                if (i == 0) acc0 = a; else if (i == 1) acc1 = a; else if (i == 2) acc2 = a; else acc3 = a;
            }
        }

#pragma unroll
        for (int i = 0; i < 4; i++) {
            int node = nb + i;
            if (node >= NN) break;
            unsigned long long a = (i == 0) ? acc0 : (i == 1) ? acc1 : (i == 2) ? acc2 : acc3;
            float2 g = unpack2(a);
            float z = 1.0f / (1.0f + __expf(-g.x));
            float r = 1.0f / (1.0f + __expf(-g.y));
            int base = node * CC + lane;
            g_z[base] = z;
            g_hr[base] = hv[i] * r;
            g_aggx[base] = axr[i];
        }
        __syncwarp();
    }
}

// ---------------- k_final: fused gather(hr) + h_tilde + h_new + head ----------
__global__ void __launch_bounds__(256) k_final(
        const float* __restrict__ x, const float* __restrict__ h,
        const float* __restrict__ Wx, const float* __restrict__ bx,
        const float* __restrict__ Wh, const float* __restrict__ bh,
        const float* __restrict__ Wl, const float* __restrict__ bl,
        float* __restrict__ out) {
    // k-pair-packed weights for gate 2: (.x = even k, .y = odd k)
    __shared__ float2 sQ[4][512];        // [mat][t*32+lane]
    __shared__ float  sIn[8 * 4 * 4 * 32];
    __shared__ float  sWl[32];
    int tid = threadIdx.x;
    for (int i = tid; i < 512; i += blockDim.x) {
        int t = i >> 5, c = i & 31;
        int o = t * 64 + c;
        sQ[0][i] = make_float2(Wx[4096 + o], Wx[4096 + o + 32]);
        sQ[1][i] = make_float2(Wx[5120 + o], Wx[5120 + o + 32]);
        sQ[2][i] = make_float2(Wh[4096 + o], Wh[4096 + o + 32]);
        sQ[3][i] = make_float2(Wh[5120 + o], Wh[5120 + o + 32]);
    }
    if (tid < 32) sWl[tid] = Wl[tid];
    __syncthreads();

    int lane = tid & 31;
    int warp = tid >> 5;
    float bias = bx[64 + lane] + bh[64 + lane];
    float blv = bl[0];

    int gw = blockIdx.x * 8 + warp;
    int stride = gridDim.x * 8 * 4;
    float* stage = &sIn[warp * 512];

    for (int nb = gw * 4; nb < NN; nb += stride) {
        // ---- stage inputs: xv, aggx, hr, agg(hr) ----
#pragma unroll
        for (int i = 0; i < 4; i++) {
            int node = nb + i;
            float xv = 0.f, axv = 0.f, hrv = 0.f, ahr = 0.f;
            if (node < NN) {
                int base = node * CC + lane;
                xv = x[base];
                axv = g_aggx[base];
                hrv = g_hr[base];
                gather1(node, lane, g_hr, ahr);
            }
            stage[i * 128 +   0 + lane] = xv;
            stage[i * 128 +  32 + lane] = axv;
            stage[i * 128 +  64 + lane] = hrv;
            stage[i * 128 +  96 + lane] = ahr;
        }
        __syncwarp();

        unsigned long long acc0 = pack2(bias, 0.0f);
        unsigned long long acc1 = acc0, acc2 = acc0, acc3 = acc0;
        const float4* st4 = (const float4*)stage;

#pragma unroll
        for (int q = 0; q < 8; q++) {
            float2 w[2][4];
#pragma unroll
            for (int tt = 0; tt < 2; tt++) {
                int row = (q * 2 + tt) * 32 + lane;
                w[tt][0] = sQ[0][row];
                w[tt][1] = sQ[1][row];
                w[tt][2] = sQ[2][row];
                w[tt][3] = sQ[3][row];
            }
#pragma unroll
            for (int i = 0; i < 4; i++) {
                unsigned long long a = (i == 0) ? acc0 : (i == 1) ? acc1 : (i == 2) ? acc2 : acc3;
                float4 vx = st4[i * 32 + 0 + q];
                float4 va = st4[i * 32 + 8 + q];
                float4 vh = st4[i * 32 + 16 + q];
                float4 vr = st4[i * 32 + 24 + q];
                fma2(a, w[0][0], vx.x, vx.y); fma2(a, w[0][1], va.x, va.y);
                fma2(a, w[0][2], vh.x, vh.y); fma2(a, w[0][3], vr.x, vr.y);
                fma2(a, w[1][0], vx.z, vx.w); fma2(a, w[1][1], va.z, va.w);
                fma2(a, w[1][2], vh.z, vh.w); fma2(a, w[1][3], vr.z, vr.w);
                if (i == 0) acc0 = a; else if (i == 1) acc1 = a; else if (i == 2) acc2 = a; else acc3 = a;
            }
        }

#pragma unroll
        for (int i = 0; i < 4; i++) {
            int node = nb + i;
            if (node >= NN) break;
            unsigned long long a = (i == 0) ? acc0 : (i == 1) ? acc1 : (i == 2) ? acc2 : acc3;
            float2 a2 = unpack2(a);
            float pre = a2.x + a2.y;
            float ht = tanhf(pre);
            int base = node * CC + lane;
            float zv = g_z[base];
            float hvv = h[base];
            float hn = zv * hvv + (1.0f - zv) * ht;

            out[NN + base] = hn;

            float rl = fmaxf(hn, 0.0f) * sWl[lane];
#pragma unroll
            for (int off = 16; off > 0; off >>= 1)
                rl += __shfl_xor_sync(0xffffffffu, rl, off);
            if (lane == 0) {
                float s = rl + blv;
                out[node] = log1pf(__expf(-fabsf(s))) + fmaxf(s, 0.0f);
            }
        }
        __syncwarp();
    }
}

// ---------------- launch ------------------------------------------------------
extern "C" void kernel_launch(void* const* d_in, const int* in_sizes, int n_in,
                              void* d_out, int out_size) {
    const float* x  = (const float*)d_in[0];
    const int*   ei = (const int*)d_in[1];
    const float* w  = (const float*)d_in[2];
    const float* h  = (const float*)d_in[3];
    const float* Wx = (const float*)d_in[4];
    const float* bx = (const float*)d_in[5];
    const float* Wh = (const float*)d_in[6];
    const float* bh = (const float*)d_in[7];
    const float* Wl = (const float*)d_in[8];
    const float* bl = (const float*)d_in[9];
    float* out = (float*)d_out;

    (void)in_sizes; (void)n_in; (void)out_size;

    k_init<<<NB, SCAN_T>>>();
    k_deg_hist<<<(EE + 255) / 256, 256>>>(ei, w);
    k_scan1<<<NB, SCAN_T>>>();
    k_scan2<<<1, 256>>>();
    k_scan3<<<NB, SCAN_T>>>();
    k_place<<<(EE + 255) / 256, 256>>>(ei, w);
    k_gates<<<592, 256>>>(x, h, Wx, bx, Wh, bh);
    k_final<<<592, 256>>>(x, h, Wx, bx, Wh, bh, Wl, bl, out);
}

// round 4
// speedup vs baseline: 1.6681x; 1.0722x over previous
#include <cuda_runtime.h>
#include <math.h>

#define NN 100000
#define EE 1600000
#define CC 32
#define SCAN_T 512
#define NB ((NN + SCAN_T - 1) / SCAN_T)   /* 196 */

// ---------------- scratch (static device globals; no allocation) -------------
__device__ float g_deg[NN];
__device__ int   g_cnt[NN];
__device__ int   g_row[NN + 1];
__device__ int   g_cur[NN];
__device__ int   g_part[256];
__device__ int2  g_csr[EE];          // (src, coef bits), grouped by dst
__device__ float g_px2[NN * CC];     // gate-2 x-side preactivation (incl. bias)
__device__ float g_z[NN * CC];
__device__ float g_hr[NN * CC];

// ---------------- f32x2 packed-FMA helpers -----------------------------------
__device__ __forceinline__ unsigned long long pack2(float a, float b) {
    unsigned long long v;
    asm("mov.b64 %0, {%1, %2};" : "=l"(v) : "f"(a), "f"(b));
    return v;
}
__device__ __forceinline__ float2 unpack2(unsigned long long v) {
    float2 r;
    asm("mov.b64 {%0, %1}, %2;" : "=f"(r.x), "=f"(r.y) : "l"(v));
    return r;
}
__device__ __forceinline__ void fma2(unsigned long long& acc, float2 w,
                                     float s0, float s1) {
    unsigned long long wv = pack2(w.x, w.y);
    unsigned long long sv = pack2(s0, s1);
    asm("fma.rn.f32x2 %0, %1, %2, %3;" : "=l"(acc) : "l"(wv), "l"(sv), "l"(acc));
}

// ---------------- k_deg_hist: 4 edges per thread ------------------------------
__global__ void k_deg_hist(const int* __restrict__ ei, const float* __restrict__ w) {
    int t = blockIdx.x * blockDim.x + threadIdx.x;
    if (t >= EE / 4) return;
    int4 s = ((const int4*)ei)[t];
    int4 d = ((const int4*)(ei + EE))[t];
    float4 wv = ((const float4*)w)[t];
    atomicAdd(&g_deg[s.x], wv.x);
    atomicAdd(&g_deg[s.y], wv.y);
    atomicAdd(&g_deg[s.z], wv.z);
    atomicAdd(&g_deg[s.w], wv.w);
    atomicAdd(&g_cnt[d.x], 1);
    atomicAdd(&g_cnt[d.y], 1);
    atomicAdd(&g_cnt[d.z], 1);
    atomicAdd(&g_cnt[d.w], 1);
}

// ---------------- scans -------------------------------------------------------
__global__ void k_scan1() {
    __shared__ int s[SCAN_T];
    int t = threadIdx.x;
    int i = blockIdx.x * SCAN_T + t;
    s[t] = (i < NN) ? g_cnt[i] : 0;
    __syncthreads();
    for (int off = SCAN_T / 2; off > 0; off >>= 1) {
        if (t < off) s[t] += s[t + off];
        __syncthreads();
    }
    if (t == 0) g_part[blockIdx.x] = s[0];
}

__global__ void k_scan2() {
    __shared__ int s[256];
    int t = threadIdx.x;
    int v = (t < NB) ? g_part[t] : 0;
    s[t] = v;
    __syncthreads();
    for (int off = 1; off < 256; off <<= 1) {
        int a = (t >= off) ? s[t - off] : 0;
        __syncthreads();
        s[t] += a;
        __syncthreads();
    }
    if (t < NB) g_part[t] = s[t] - v;   // exclusive
}

__global__ void k_scan3() {
    __shared__ int s[SCAN_T];
    int t = threadIdx.x;
    int i = blockIdx.x * SCAN_T + t;
    int v = (i < NN) ? g_cnt[i] : 0;
    s[t] = v;
    __syncthreads();
    for (int off = 1; off < SCAN_T; off <<= 1) {
        int a = (t >= off) ? s[t - off] : 0;
        __syncthreads();
        s[t] += a;
        __syncthreads();
    }
    if (i < NN) {
        int rs = g_part[blockIdx.x] + s[t] - v;
        g_row[i] = rs;
        g_cur[i] = rs;
    }
    if (blockIdx.x == 0 && t == 0) g_row[NN] = EE;
}

// ---------------- k_place: 4 edges per thread ---------------------------------
__global__ void k_place(const int* __restrict__ ei, const float* __restrict__ w) {
    int t = blockIdx.x * blockDim.x + threadIdx.x;
    if (t >= EE / 4) return;
    int4 s = ((const int4*)ei)[t];
    int4 d = ((const int4*)(ei + EE))[t];
    float4 wv = ((const float4*)w)[t];
    float ds0 = g_deg[s.x], ds1 = g_deg[s.y], ds2 = g_deg[s.z], ds3 = g_deg[s.w];
    float dd0 = g_deg[d.x], dd1 = g_deg[d.y], dd2 = g_deg[d.z], dd3 = g_deg[d.w];
    float c0 = -((ds0 > 0.f ? rsqrtf(ds0) : 0.f) * wv.x * (dd0 > 0.f ? rsqrtf(dd0) : 0.f));
    float c1 = -((ds1 > 0.f ? rsqrtf(ds1) : 0.f) * wv.y * (dd1 > 0.f ? rsqrtf(dd1) : 0.f));
    float c2 = -((ds2 > 0.f ? rsqrtf(ds2) : 0.f) * wv.z * (dd2 > 0.f ? rsqrtf(dd2) : 0.f));
    float c3 = -((ds3 > 0.f ? rsqrtf(ds3) : 0.f) * wv.w * (dd3 > 0.f ? rsqrtf(dd3) : 0.f));
    int p0 = atomicAdd(&g_cur[d.x], 1);
    int p1 = atomicAdd(&g_cur[d.y], 1);
    int p2 = atomicAdd(&g_cur[d.z], 1);
    int p3 = atomicAdd(&g_cur[d.w], 1);
    g_csr[p0] = make_int2(s.x, __float_as_int(c0));
    g_csr[p1] = make_int2(s.y, __float_as_int(c1));
    g_csr[p2] = make_int2(s.z, __float_as_int(c2));
    g_csr[p3] = make_int2(s.w, __float_as_int(c3));
}

// ---------------- gathers (unroll 8 for MLP) -----------------------------------
__device__ __forceinline__ void gather2(int node, int lane,
                                        const float* __restrict__ a,
                                        const float* __restrict__ b,
                                        float& ra, float& rb) {
    int beg = g_row[node], end = g_row[node + 1];
    float sa = 0.0f, sb = 0.0f;
    int e = beg;
    for (; e + 8 <= end; e += 8) {
        int2 t0 = g_csr[e],     t1 = g_csr[e + 1], t2 = g_csr[e + 2], t3 = g_csr[e + 3];
        int2 t4 = g_csr[e + 4], t5 = g_csr[e + 5], t6 = g_csr[e + 6], t7 = g_csr[e + 7];
        float a0 = a[t0.x * CC + lane], a1 = a[t1.x * CC + lane];
        float a2 = a[t2.x * CC + lane], a3 = a[t3.x * CC + lane];
        float a4 = a[t4.x * CC + lane], a5 = a[t5.x * CC + lane];
        float a6 = a[t6.x * CC + lane], a7 = a[t7.x * CC + lane];
        float b0 = b[t0.x * CC + lane], b1 = b[t1.x * CC + lane];
        float b2 = b[t2.x * CC + lane], b3 = b[t3.x * CC + lane];
        float b4 = b[t4.x * CC + lane], b5 = b[t5.x * CC + lane];
        float b6 = b[t6.x * CC + lane], b7 = b[t7.x * CC + lane];
        sa += __int_as_float(t0.y) * a0 + __int_as_float(t1.y) * a1
            + __int_as_float(t2.y) * a2 + __int_as_float(t3.y) * a3
            + __int_as_float(t4.y) * a4 + __int_as_float(t5.y) * a5
            + __int_as_float(t6.y) * a6 + __int_as_float(t7.y) * a7;
        sb += __int_as_float(t0.y) * b0 + __int_as_float(t1.y) * b1
            + __int_as_float(t2.y) * b2 + __int_as_float(t3.y) * b3
            + __int_as_float(t4.y) * b4 + __int_as_float(t5.y) * b5
            + __int_as_float(t6.y) * b6 + __int_as_float(t7.y) * b7;
    }
    for (; e < end; e++) {
        int2 t = g_csr[e];
        float c = __int_as_float(t.y);
        sa += c * a[t.x * CC + lane];
        sb += c * b[t.x * CC + lane];
    }
    ra = sa; rb = sb;
}

__device__ __forceinline__ void gather1(int node, int lane,
                                        const float* __restrict__ a, float& ra) {
    int beg = g_row[node], end = g_row[node + 1];
    float sa = 0.0f;
    int e = beg;
    for (; e + 8 <= end; e += 8) {
        int2 t0 = g_csr[e],     t1 = g_csr[e + 1], t2 = g_csr[e + 2], t3 = g_csr[e + 3];
        int2 t4 = g_csr[e + 4], t5 = g_csr[e + 5], t6 = g_csr[e + 6], t7 = g_csr[e + 7];
        float a0 = a[t0.x * CC + lane], a1 = a[t1.x * CC + lane];
        float a2 = a[t2.x * CC + lane], a3 = a[t3.x * CC + lane];
        float a4 = a[t4.x * CC + lane], a5 = a[t5.x * CC + lane];
        float a6 = a[t6.x * CC + lane], a7 = a[t7.x * CC + lane];
        sa += __int_as_float(t0.y) * a0 + __int_as_float(t1.y) * a1
            + __int_as_float(t2.y) * a2 + __int_as_float(t3.y) * a3
            + __int_as_float(t4.y) * a4 + __int_as_float(t5.y) * a5
            + __int_as_float(t6.y) * a6 + __int_as_float(t7.y) * a7;
    }
    for (; e < end; e++) {
        int2 t = g_csr[e];
        sa += __int_as_float(t.y) * a[t.x * CC + lane];
    }
    ra = sa;
}

// ---------------- k_gates: gather(x,h) + gates z,r + px2 (4 nodes/warp) -------
// dyn smem: sW[4][1024] float2 (gate-pair z/r), sQ[2][512] float2 (k-pair gate2 x)
__global__ void __launch_bounds__(256) k_gates(
        const float* __restrict__ x, const float* __restrict__ h,
        const float* __restrict__ Wx, const float* __restrict__ bx,
        const float* __restrict__ Wh, const float* __restrict__ bh) {
    extern __shared__ float2 dynw[];
    float2* sW0 = dynw;            // Wx[*,0] pairs (z,r)
    float2* sW1 = dynw + 1024;     // Wx[*,1]
    float2* sW2 = dynw + 2048;     // Wh[*,0]
    float2* sW3 = dynw + 3072;     // Wh[*,1]
    float2* sQ0 = dynw + 4096;     // Wx[2,0] k-pairs
    float2* sQ1 = dynw + 4608;     // Wx[2,1] k-pairs
    __shared__ __align__(16) float sIn[8 * 4 * 4 * 32];

    int tid = threadIdx.x;
    for (int i = tid; i < 1024; i += blockDim.x) {
        sW0[i] = make_float2(Wx[i],        Wx[2048 + i]);
        sW1[i] = make_float2(Wx[1024 + i], Wx[3072 + i]);
        sW2[i] = make_float2(Wh[i],        Wh[2048 + i]);
        sW3[i] = make_float2(Wh[1024 + i], Wh[3072 + i]);
    }
    for (int i = tid; i < 512; i += blockDim.x) {
        int t = i >> 5, c = i & 31;
        int o = t * 64 + c;
        sQ0[i] = make_float2(Wx[4096 + o], Wx[4096 + o + 32]);
        sQ1[i] = make_float2(Wx[5120 + o], Wx[5120 + o + 32]);
    }
    __syncthreads();

    int lane = tid & 31;
    int warp = tid >> 5;
    float bz = bx[lane] + bh[lane];
    float br = bx[32 + lane] + bh[32 + lane];
    float b2 = bx[64 + lane] + bh[64 + lane];

    int gw = blockIdx.x * 8 + warp;
    int stride = gridDim.x * 8 * 4;
    float* stage = &sIn[warp * 512];

    for (int nb = gw * 4; nb < NN; nb += stride) {
        float hv[4];
#pragma unroll
        for (int i = 0; i < 4; i++) {
            int node = nb + i;
            float xv = 0.f, hvv = 0.f, ax = 0.f, ah = 0.f;
            if (node < NN) {
                int base = node * CC + lane;
                xv = x[base];
                hvv = h[base];
                gather2(node, lane, x, h, ax, ah);
            }
            hv[i] = hvv;
            stage[i * 128 +  0 + lane] = xv;
            stage[i * 128 + 32 + lane] = ax;
            stage[i * 128 + 64 + lane] = hvv;
            stage[i * 128 + 96 + lane] = ah;
        }
        __syncwarp();

        unsigned long long acc0 = pack2(bz, br);
        unsigned long long acc1 = acc0, acc2 = acc0, acc3 = acc0;
        unsigned long long p0 = pack2(b2, 0.f), p1 = p0, p2 = p0, p3 = p0;
        const float4* st4 = (const float4*)stage;

#pragma unroll
        for (int q = 0; q < 8; q++) {
            float2 w[4][4];
#pragma unroll
            for (int kk = 0; kk < 4; kk++) {
                int row = (q * 4 + kk) * 32 + lane;
                w[kk][0] = sW0[row];
                w[kk][1] = sW1[row];
                w[kk][2] = sW2[row];
                w[kk][3] = sW3[row];
            }
            float2 q0a = sQ0[(2 * q) * 32 + lane];
            float2 q0b = sQ1[(2 * q) * 32 + lane];
            float2 q1a = sQ0[(2 * q + 1) * 32 + lane];
            float2 q1b = sQ1[(2 * q + 1) * 32 + lane];
#pragma unroll
            for (int i = 0; i < 4; i++) {
                unsigned long long a = (i == 0) ? acc0 : (i == 1) ? acc1 : (i == 2) ? acc2 : acc3;
                unsigned long long p = (i == 0) ? p0 : (i == 1) ? p1 : (i == 2) ? p2 : p3;
                float4 vx = st4[i * 32 +  0 + q];
                float4 va = st4[i * 32 +  8 + q];
                float4 vh = st4[i * 32 + 16 + q];
                float4 vr = st4[i * 32 + 24 + q];
                fma2(a, w[0][0], vx.x, vx.x); fma2(a, w[0][1], va.x, va.x);
                fma2(a, w[0][2], vh.x, vh.x); fma2(a, w[0][3], vr.x, vr.x);
                fma2(a, w[1][0], vx.y, vx.y); fma2(a, w[1][1], va.y, va.y);
                fma2(a, w[1][2], vh.y, vh.y); fma2(a, w[1][3], vr.y, vr.y);
                fma2(a, w[2][0], vx.z, vx.z); fma2(a, w[2][1], va.z, va.z);
                fma2(a, w[2][2], vh.z, vh.z); fma2(a, w[2][3], vr.z, vr.z);
                fma2(a, w[3][0], vx.w, vx.w); fma2(a, w[3][1], va.w, va.w);
                fma2(a, w[3][2], vh.w, vh.w); fma2(a, w[3][3], vr.w, vr.w);
                fma2(p, q0a, vx.x, vx.y); fma2(p, q0b, va.x, va.y);
                fma2(p, q1a, vx.z, vx.w); fma2(p, q1b, va.z, va.w);
                if (i == 0) { acc0 = a; p0 = p; } else if (i == 1) { acc1 = a; p1 = p; }
                else if (i == 2) { acc2 = a; p2 = p; } else { acc3 = a; p3 = p; }
            }
        }

#pragma unroll
        for (int i = 0; i < 4; i++) {
            int node = nb + i;
            if (node >= NN) break;
            unsigned long long a = (i == 0) ? acc0 : (i == 1) ? acc1 : (i == 2) ? acc2 : acc3;
            unsigned long long p = (i == 0) ? p0 : (i == 1) ? p1 : (i == 2) ? p2 : p3;
            float2 g = unpack2(a);
            float2 pp = unpack2(p);
            float z = 1.0f / (1.0f + __expf(-g.x));
            float r = 1.0f / (1.0f + __expf(-g.y));
            int base = node * CC + lane;
            g_z[base] = z;
            g_hr[base] = hv[i] * r;
            g_px2[base] = pp.x + pp.y;
        }
        __syncwarp();
    }
}

// ---------------- k_final: gather(hr) + h_tilde + h_new + head ----------------
// dyn smem: sQ[2][512] float2 (k-pair gate2 h)
__global__ void __launch_bounds__(256) k_final(
        const float* __restrict__ h,
        const float* __restrict__ Wh,
        const float* __restrict__ Wl, const float* __restrict__ bl,
        float* __restrict__ out) {
    extern __shared__ float2 dynw[];
    float2* sQ0 = dynw;          // Wh[2,0] k-pairs
    float2* sQ1 = dynw + 512;    // Wh[2,1] k-pairs
    __shared__ __align__(16) float sIn[8 * 4 * 2 * 32];
    __shared__ float sWl[32];

    int tid = threadIdx.x;
    for (int i = tid; i < 512; i += blockDim.x) {
        int t = i >> 5, c = i & 31;
        int o = t * 64 + c;
        sQ0[i] = make_float2(Wh[4096 + o], Wh[4096 + o + 32]);
        sQ1[i] = make_float2(Wh[5120 + o], Wh[5120 + o + 32]);
    }
    if (tid < 32) sWl[tid] = Wl[tid];
    __syncthreads();

    int lane = tid & 31;
    int warp = tid >> 5;
    float blv = bl[0];

    int gw = blockIdx.x * 8 + warp;
    int stride = gridDim.x * 8 * 4;
    float* stage = &sIn[warp * 256];

    for (int nb = gw * 4; nb < NN; nb += stride) {
        float px2r[4];
#pragma unroll
        for (int i = 0; i < 4; i++) {
            int node = nb + i;
            float hrv = 0.f, ahr = 0.f, px = 0.f;
            if (node < NN) {
                int base = node * CC + lane;
                hrv = g_hr[base];
                px = g_px2[base];
                gather1(node, lane, g_hr, ahr);
            }
            px2r[i] = px;
            stage[i * 64 +  0 + lane] = hrv;
            stage[i * 64 + 32 + lane] = ahr;
        }
        __syncwarp();

        unsigned long long acc0 = pack2(px2r[0], 0.f);
        unsigned long long acc1 = pack2(px2r[1], 0.f);
        unsigned long long acc2 = pack2(px2r[2], 0.f);
        unsigned long long acc3 = pack2(px2r[3], 0.f);
        const float4* st4 = (const float4*)stage;

#pragma unroll
        for (int q = 0; q < 8; q++) {
            float2 w0a = sQ0[(2 * q) * 32 + lane];
            float2 w0b = sQ1[(2 * q) * 32 + lane];
            float2 w1a = sQ0[(2 * q + 1) * 32 + lane];
            float2 w1b = sQ1[(2 * q + 1) * 32 + lane];
#pragma unroll
            for (int i = 0; i < 4; i++) {
                unsigned long long a = (i == 0) ? acc0 : (i == 1) ? acc1 : (i == 2) ? acc2 : acc3;
                float4 vh = st4[i * 16 + 0 + q];
                float4 vr = st4[i * 16 + 8 + q];
                fma2(a, w0a, vh.x, vh.y); fma2(a, w0b, vr.x, vr.y);
                fma2(a, w1a, vh.z, vh.w); fma2(a, w1b, vr.z, vr.w);
                if (i == 0) acc0 = a; else if (i == 1) acc1 = a; else if (i == 2) acc2 = a; else acc3 = a;
            }
        }

#pragma unroll
        for (int i = 0; i < 4; i++) {
            int node = nb + i;
            if (node >= NN) break;
            unsigned long long a = (i == 0) ? acc0 : (i == 1) ? acc1 : (i == 2) ? acc2 : acc3;
            float2 a2 = unpack2(a);
            float ht = tanhf(a2.x + a2.y);
            int base = node * CC + lane;
            float zv = g_z[base];
            float hvv = h[base];
            float hn = zv * hvv + (1.0f - zv) * ht;

            out[NN + base] = hn;

            float rl = fmaxf(hn, 0.0f) * sWl[lane];
#pragma unroll
            for (int off = 16; off > 0; off >>= 1)
                rl += __shfl_xor_sync(0xffffffffu, rl, off);
            if (lane == 0) {
                float s = rl + blv;
                out[node] = log1pf(__expf(-fabsf(s))) + fmaxf(s, 0.0f);
            }
        }
        __syncwarp();
    }
}

// ---------------- launch ------------------------------------------------------
extern "C" void kernel_launch(void* const* d_in, const int* in_sizes, int n_in,
                              void* d_out, int out_size) {
    const float* x  = (const float*)d_in[0];
    const int*   ei = (const int*)d_in[1];
    const float* w  = (const float*)d_in[2];
    const float* h  = (const float*)d_in[3];
    const float* Wx = (const float*)d_in[4];
    const float* bx = (const float*)d_in[5];
    const float* Wh = (const float*)d_in[6];
    const float* bh = (const float*)d_in[7];
    const float* Wl = (const float*)d_in[8];
    const float* bl = (const float*)d_in[9];
    float* out = (float*)d_out;

    (void)in_sizes; (void)n_in; (void)out_size;

    cudaFuncSetAttribute(k_gates, cudaFuncAttributeMaxDynamicSharedMemorySize, 5120 * 8);
    cudaFuncSetAttribute(k_final, cudaFuncAttributeMaxDynamicSharedMemorySize, 1024 * 8);

    void* p_deg = nullptr; cudaGetSymbolAddress(&p_deg, g_deg);
    void* p_cnt = nullptr; cudaGetSymbolAddress(&p_cnt, g_cnt);
    cudaMemsetAsync(p_deg, 0, NN * sizeof(float));
    cudaMemsetAsync(p_cnt, 0, NN * sizeof(int));

    k_deg_hist<<<(EE / 4 + 255) / 256, 256>>>(ei, w);
    k_scan1<<<NB, SCAN_T>>>();
    k_scan2<<<1, 256>>>();
    k_scan3<<<NB, SCAN_T>>>();
    k_place<<<(EE / 4 + 255) / 256, 256>>>(ei, w);
    k_gates<<<592, 256, 5120 * 8>>>(x, h, Wx, bx, Wh, bh);
    k_final<<<592, 256, 1024 * 8>>>(h, Wh, Wl, bl, out);
}